// round 9
// baseline (speedup 1.0000x reference)
#include <cuda_runtime.h>
#include <cuda_fp16.h>
#include <cstdint>
#include <math.h>

#define N_NODES 50000
#define N_EDGES 625000
#define N_GRAPHS 256
#define CH 128
#define N_OUT 10

// ---------------- scratch (no allocations allowed) ----------------
__device__ __half g_xh[N_NODES * CH];
__device__ __half g_hA[N_NODES * CH];
__device__ __half g_hB[N_NODES * CH];
__device__ __half g_Wh[9 * CH * CH];   // fp16, transposed [n][k]

__device__ int   g_deg   [N_NODES];
__device__ int   g_cursor[N_NODES];
__device__ int   g_rowptr[N_NODES + 1];
__device__ int   g_csrsrc[N_EDGES];
__device__ int   g_bsums [64];

// ---------------- utility ----------------
__global__ void zero_deg_cursor(int* deg, int* cursor) {
    int i = blockIdx.x * blockDim.x + threadIdx.x;
    if (i < N_NODES) { deg[i] = 0; cursor[i] = 0; }
}

__global__ void xh_prep(const float* __restrict__ x, __half* __restrict__ xh) {
    int i = blockIdx.x * blockDim.x + threadIdx.x;
    if (i >= (N_NODES * CH) / 4) return;
    float4 v = *(const float4*)(x + i * 4);
    __half2 h0 = __floats2half2_rn(v.x, v.y);
    __half2 h1 = __floats2half2_rn(v.z, v.w);
    uint2 o;
    o.x = *(uint32_t*)&h0;
    o.y = *(uint32_t*)&h1;
    *(uint2*)(xh + i * 4) = o;
}

// ---------------- W transpose + fp16 convert ----------------
__global__ void wh_prep(const float* __restrict__ W, __half* __restrict__ Wh) {
    __shared__ float tile[32][33];
    int g = blockIdx.z;
    int tx = threadIdx.x, ty = threadIdx.y;
    int kt = blockIdx.x * 32, nt = blockIdx.y * 32;
    const float* Wg = W + g * CH * CH;
    __half* Whg = Wh + g * CH * CH;
#pragma unroll
    for (int i = 0; i < 32; i += 8)
        tile[ty + i][tx] = Wg[(kt + ty + i) * CH + nt + tx];
    __syncthreads();
#pragma unroll
    for (int i = 0; i < 32; i += 8)
        Whg[(nt + ty + i) * CH + kt + tx] = __float2half_rn(tile[tx][ty + i]);
}

// ---------------- CSR build ----------------
__global__ void count_deg(const int* __restrict__ dst, int* __restrict__ deg) {
    int i = blockIdx.x * blockDim.x + threadIdx.x;
    if (i >= N_EDGES / 4) return;
    int4 d = ((const int4*)dst)[i];
    atomicAdd(&deg[d.x], 1);
    atomicAdd(&deg[d.y], 1);
    atomicAdd(&deg[d.z], 1);
    atomicAdd(&deg[d.w], 1);
}

__global__ void scan_blocks(const int* __restrict__ deg, int* __restrict__ rowptr,
                            int* __restrict__ bsums) {
    __shared__ int wsum[32];
    int gid = blockIdx.x * 1024 + threadIdx.x;
    int v = (gid < N_NODES) ? deg[gid] : 0;
    int lane = threadIdx.x & 31, wid = threadIdx.x >> 5;
    int x = v;
#pragma unroll
    for (int o = 1; o < 32; o <<= 1) {
        int y = __shfl_up_sync(0xffffffffu, x, o);
        if (lane >= o) x += y;
    }
    if (lane == 31) wsum[wid] = x;
    __syncthreads();
    if (wid == 0) {
        int s = wsum[lane];
#pragma unroll
        for (int o = 1; o < 32; o <<= 1) {
            int y = __shfl_up_sync(0xffffffffu, s, o);
            if (lane >= o) s += y;
        }
        wsum[lane] = s;
    }
    __syncthreads();
    int base = (wid > 0) ? wsum[wid - 1] : 0;
    int incl = base + x;
    if (gid < N_NODES) rowptr[gid] = incl - v;
    if (threadIdx.x == 1023) bsums[blockIdx.x] = incl;
}

__global__ void add_boff(int* __restrict__ rowptr, const int* __restrict__ bsums, int nblocks) {
    __shared__ int pre;
    if (threadIdx.x == 0) {
        int run = 0;
        for (int i = 0; i < (int)blockIdx.x; i++) run += bsums[i];
        pre = run;
        if ((int)blockIdx.x == nblocks - 1)
            rowptr[N_NODES] = run + bsums[nblocks - 1];
    }
    __syncthreads();
    int gid = blockIdx.x * 1024 + threadIdx.x;
    if (gid < N_NODES) rowptr[gid] += pre;
}

__global__ void scatter_edges(const int* __restrict__ src, const int* __restrict__ dst,
                              const int* __restrict__ rowptr, int* __restrict__ cursor,
                              int* __restrict__ csrsrc) {
    int e = blockIdx.x * blockDim.x + threadIdx.x;
    if (e >= N_EDGES) return;
    int d = dst[e];
    int slot = rowptr[d] + atomicAdd(&cursor[d], 1);
    csrsrc[slot] = src[e];
}

// ---------------- fused agg + 3-layer MLP ----------------------------------
// For each node v in the CTA's 64 rows: z = hin[v] + sum_{u->v} hin[u] (fp32
// accum, fp16 into smem), then 3 GEMM layers in smem, out to global.
#define HS 136
#define ACT_SZ (64 * HS)
#define WB_SZ  (128 * HS)
#define MLP_SMEM ((2 * ACT_SZ + 2 * WB_SZ) * 2)   // 104448 B

__device__ __forceinline__ void mma16816(float* d, uint32_t a0, uint32_t a1,
                                         uint32_t a2, uint32_t a3,
                                         uint32_t b0, uint32_t b1) {
    asm volatile(
        "mma.sync.aligned.m16n8k16.row.col.f32.f16.f16.f32 "
        "{%0,%1,%2,%3}, {%4,%5,%6,%7}, {%8,%9}, {%0,%1,%2,%3};"
        : "+f"(d[0]), "+f"(d[1]), "+f"(d[2]), "+f"(d[3])
        : "r"(a0), "r"(a1), "r"(a2), "r"(a3), "r"(b0), "r"(b1));
}

__device__ __forceinline__ void ldsm_x4(uint32_t& r0, uint32_t& r1, uint32_t& r2,
                                        uint32_t& r3, uint32_t addr) {
    asm volatile("ldmatrix.sync.aligned.m8n8.x4.shared.b16 {%0,%1,%2,%3}, [%4];"
        : "=r"(r0), "=r"(r1), "=r"(r2), "=r"(r3) : "r"(addr));
}

__device__ __forceinline__ void cp_async16(uint32_t saddr, const void* gptr, int src_sz) {
    asm volatile("cp.async.cg.shared.global [%0], [%1], 16, %2;"
        :: "r"(saddr), "l"(gptr), "r"(src_sz));
}

__global__ __launch_bounds__(256) void gin_layer(
    const __half* __restrict__ hin, const __half* __restrict__ Wh3,
    const float* __restrict__ bias3,
    const int* __restrict__ rowptr, const int* __restrict__ csrsrc,
    __half* __restrict__ C, int M)
{
    extern __shared__ __align__(16) char smem[];
    __half* actBuf = (__half*)smem;                 // [2][64][HS]
    __half* wBuf   = actBuf + 2 * ACT_SZ;           // [2][128][HS]

    int tid = threadIdx.x;
    int row0 = blockIdx.x * 64;

    uint32_t actB = (uint32_t)__cvta_generic_to_shared(actBuf);
    uint32_t wB   = (uint32_t)__cvta_generic_to_shared(wBuf);

    // kick off W0 + W1 prefetch first (overlaps with the gather below)
#pragma unroll
    for (int it = 0; it < 8; it++) {
        int q = tid + it * 256;
        int n = q >> 4, k8 = q & 15;
        cp_async16(wB + ((n * HS + k8 * 8) << 1),
                   Wh3 + (size_t)n * 128 + k8 * 8, 16);
    }
    asm volatile("cp.async.commit_group;");
#pragma unroll
    for (int it = 0; it < 8; it++) {
        int q = tid + it * 256;
        int n = q >> 4, k8 = q & 15;
        cp_async16(wB + ((WB_SZ + n * HS + k8 * 8) << 1),
                   Wh3 + CH * CH + (size_t)n * 128 + k8 * 8, 16);
    }
    asm volatile("cp.async.commit_group;");

    // gather: warp w handles rows w*8 .. w*8+7; lane covers 4 channels
    {
        int wgw = tid >> 5, lane = tid & 31;
        const uint2* hv = (const uint2*)hin;
#pragma unroll
        for (int rr = 0; rr < 8; rr++) {
            int r = wgw * 8 + rr;
            int node = row0 + r;
            float2 a0 = make_float2(0.f, 0.f), a1 = make_float2(0.f, 0.f);
            if (node < M) {
                uint2 s = hv[(size_t)node * 32 + lane];
                a0 = __half22float2(*(__half2*)&s.x);
                a1 = __half22float2(*(__half2*)&s.y);
                int beg = rowptr[node], end = rowptr[node + 1];
                int i = beg;
                for (; i + 1 < end; i += 2) {
                    int s0 = csrsrc[i], s1 = csrsrc[i + 1];
                    uint2 w0 = hv[(size_t)s0 * 32 + lane];
                    uint2 w1 = hv[(size_t)s1 * 32 + lane];
                    float2 u0 = __half22float2(*(__half2*)&w0.x);
                    float2 u1 = __half22float2(*(__half2*)&w0.y);
                    float2 v0 = __half22float2(*(__half2*)&w1.x);
                    float2 v1 = __half22float2(*(__half2*)&w1.y);
                    a0.x += u0.x + v0.x; a0.y += u0.y + v0.y;
                    a1.x += u1.x + v1.x; a1.y += u1.y + v1.y;
                }
                if (i < end) {
                    int s0 = csrsrc[i];
                    uint2 w0 = hv[(size_t)s0 * 32 + lane];
                    float2 u0 = __half22float2(*(__half2*)&w0.x);
                    float2 u1 = __half22float2(*(__half2*)&w0.y);
                    a0.x += u0.x; a0.y += u0.y; a1.x += u1.x; a1.y += u1.y;
                }
            }
            __half2 o0 = __floats2half2_rn(a0.x, a0.y);
            __half2 o1 = __floats2half2_rn(a1.x, a1.y);
            uint2 o;
            o.x = *(uint32_t*)&o0;
            o.y = *(uint32_t*)&o1;
            *(uint2*)(actBuf + r * HS + lane * 4) = o;
        }
    }
    asm volatile("cp.async.wait_group 1;");   // W0 ready (W1 still in flight)
    __syncthreads();

    int lane = tid & 31, w = tid >> 5;
    int wm = w >> 2, wn = w & 3;               // 2(M) x 4(N)
    int m0 = wm * 32, n0 = wn * 32;
    int grp = lane >> 2, tig = lane & 3;

    uint32_t aPat[2], bPat[2];
#pragma unroll
    for (int mt = 0; mt < 2; mt++)
        aPat[mt] = (uint32_t)((m0 + mt * 16 + (lane & 15)) * HS + (lane >> 4) * 8);
#pragma unroll
    for (int jj = 0; jj < 2; jj++)
        bPat[jj] = (uint32_t)((n0 + jj * 16 + (lane & 7) + ((lane >> 4) << 3)) * HS +
                              ((lane >> 3) & 1) * 8);

#pragma unroll
    for (int l = 0; l < 3; l++) {
        uint32_t aBase = actB + ((l & 1) ? (ACT_SZ << 1) : 0);
        uint32_t bBase = wB + ((l & 1) ? (WB_SZ << 1) : 0);

        float acc[2][4][4];
#pragma unroll
        for (int mt = 0; mt < 2; mt++)
#pragma unroll
            for (int j = 0; j < 4; j++)
#pragma unroll
                for (int i = 0; i < 4; i++) acc[mt][j][i] = 0.0f;

#pragma unroll
        for (int ks = 0; ks < 8; ks++) {
            uint32_t af[2][4];
#pragma unroll
            for (int mt = 0; mt < 2; mt++)
                ldsm_x4(af[mt][0], af[mt][1], af[mt][2], af[mt][3],
                        aBase + (aPat[mt] << 1) + ks * 32);
#pragma unroll
            for (int jj = 0; jj < 2; jj++) {
                uint32_t b0, b1, b2, b3;
                ldsm_x4(b0, b1, b2, b3, bBase + (bPat[jj] << 1) + ks * 32);
                mma16816(acc[0][jj * 2],     af[0][0], af[0][1], af[0][2], af[0][3], b0, b1);
                mma16816(acc[1][jj * 2],     af[1][0], af[1][1], af[1][2], af[1][3], b0, b1);
                mma16816(acc[0][jj * 2 + 1], af[0][0], af[0][1], af[0][2], af[0][3], b2, b3);
                mma16816(acc[1][jj * 2 + 1], af[1][0], af[1][1], af[1][2], af[1][3], b2, b3);
            }
        }

        const float* bias = bias3 + l * CH;
        if (l < 2) {
            __syncthreads();
            __half* actN = actBuf + ((l & 1) ? 0 : ACT_SZ);
#pragma unroll
            for (int mt = 0; mt < 2; mt++) {
                int rloc = m0 + mt * 16 + grp;
#pragma unroll
                for (int j = 0; j < 4; j++) {
                    int c = n0 + (j >> 1) * 16 + (j & 1) * 8 + tig * 2;
                    float bx = __ldg(bias + c), by = __ldg(bias + c + 1);
                    float v0 = fmaxf(acc[mt][j][0] + bx, 0.f);
                    float v1 = fmaxf(acc[mt][j][1] + by, 0.f);
                    float v2 = fmaxf(acc[mt][j][2] + bx, 0.f);
                    float v3 = fmaxf(acc[mt][j][3] + by, 0.f);
                    *(__half2*)(actN + rloc * HS + c)       = __floats2half2_rn(v0, v1);
                    *(__half2*)(actN + (rloc + 8) * HS + c) = __floats2half2_rn(v2, v3);
                }
            }
            if (l == 0) {
                // prefetch W2 into wbuf[0] (W0 reads done after the sync above)
#pragma unroll
                for (int it = 0; it < 8; it++) {
                    int q = tid + it * 256;
                    int n = q >> 4, k8 = q & 15;
                    cp_async16(wB + ((n * HS + k8 * 8) << 1),
                               Wh3 + 2 * CH * CH + (size_t)n * 128 + k8 * 8, 16);
                }
                asm volatile("cp.async.commit_group;");
                asm volatile("cp.async.wait_group 1;");   // W1 ready
            } else {
                asm volatile("cp.async.wait_group 0;");   // W2 ready
            }
            __syncthreads();
        } else {
#pragma unroll
            for (int mt = 0; mt < 2; mt++) {
                int r = row0 + m0 + mt * 16 + grp;
#pragma unroll
                for (int j = 0; j < 4; j++) {
                    int c = n0 + (j >> 1) * 16 + (j & 1) * 8 + tig * 2;
                    float bx = __ldg(bias + c), by = __ldg(bias + c + 1);
                    if (r < M)
                        *(__half2*)(C + (size_t)r * 128 + c) =
                            __floats2half2_rn(acc[mt][j][0] + bx, acc[mt][j][1] + by);
                    if (r + 8 < M)
                        *(__half2*)(C + (size_t)(r + 8) * 128 + c) =
                            __floats2half2_rn(acc[mt][j][2] + bx, acc[mt][j][3] + by);
                }
            }
        }
    }
}

// ---------------- fused pool (sorted segments) + head ----------------------
__global__ void pool_head(const __half* __restrict__ h, const int* __restrict__ gid,
                          const float* __restrict__ W1, const float* __restrict__ b1,
                          const float* __restrict__ W2, const float* __restrict__ b2,
                          float* __restrict__ out) {
    int g = blockIdx.x;
    int t = threadIdx.x;
    __shared__ float p[128];
    __shared__ float h1[128];
    __shared__ float logits[N_OUT];

    int lo = 0, hi = N_NODES;
    while (lo < hi) { int mid = (lo + hi) >> 1; if (gid[mid] < g) lo = mid + 1; else hi = mid; }
    int start = lo;
    lo = start; hi = N_NODES;
    while (lo < hi) { int mid = (lo + hi) >> 1; if (gid[mid] < g + 1) lo = mid + 1; else hi = mid; }
    int end = lo;

    float s = 0.0f;
    for (int n = start; n < end; n++)
        s += __half2float(h[(size_t)n * 128 + t]);
    int cnt = end - start;
    p[t] = s / fmaxf((float)cnt, 1.0f);
    __syncthreads();

    float acc = b1[t];
#pragma unroll 8
    for (int k = 0; k < 128; k++) acc += p[k] * W1[k * 128 + t];
    h1[t] = fmaxf(acc, 0.0f);
    __syncthreads();

    if (t < N_OUT) {
        float a = b2[t];
#pragma unroll 8
        for (int k = 0; k < 128; k++) a += h1[k] * W2[k * N_OUT + t];
        logits[t] = a;
    }
    __syncthreads();

    if (t == 0) {
        float m = -1e30f;
#pragma unroll
        for (int o = 0; o < N_OUT; o++) m = fmaxf(m, logits[o]);
        float e[N_OUT], sum = 0.0f;
#pragma unroll
        for (int o = 0; o < N_OUT; o++) { e[o] = __expf(logits[o] - m); sum += e[o]; }
        float inv = 1.0f / sum;
#pragma unroll
        for (int o = 0; o < N_OUT; o++) out[g * N_OUT + o] = e[o] * inv;
    }
}

// ---------------- launch ----------------
extern "C" void kernel_launch(void* const* d_in, const int* in_sizes, int n_in,
                              void* d_out, int out_size) {
    const float* x        = (const float*)d_in[0];
    const int*   edge_src = (const int*)  d_in[1];
    const int*   edge_dst = (const int*)  d_in[2];
    const int*   graph_id = (const int*)  d_in[3];
    const float* conv_W   = (const float*)d_in[4];
    const float* conv_b   = (const float*)d_in[5];
    const float* d1_W     = (const float*)d_in[6];
    const float* d1_b     = (const float*)d_in[7];
    const float* d2_W     = (const float*)d_in[8];
    const float* d2_b     = (const float*)d_in[9];
    float* out = (float*)d_out;

    __half *xh, *hA, *hB, *Wh;
    int *deg, *cursor, *rowptr, *csrsrc, *bsums;
    cudaGetSymbolAddress((void**)&xh,     g_xh);
    cudaGetSymbolAddress((void**)&hA,     g_hA);
    cudaGetSymbolAddress((void**)&hB,     g_hB);
    cudaGetSymbolAddress((void**)&Wh,     g_Wh);
    cudaGetSymbolAddress((void**)&deg,    g_deg);
    cudaGetSymbolAddress((void**)&cursor, g_cursor);
    cudaGetSymbolAddress((void**)&rowptr, g_rowptr);
    cudaGetSymbolAddress((void**)&csrsrc, g_csrsrc);
    cudaGetSymbolAddress((void**)&bsums,  g_bsums);

    cudaFuncSetAttribute(gin_layer, cudaFuncAttributeMaxDynamicSharedMemorySize, MLP_SMEM);

    const int TB = 256;
    const int scanBlocks = (N_NODES + 1023) / 1024;  // 49
    const int mlpBlocks  = (N_NODES + 63) / 64;      // 782

    wh_prep<<<dim3(4, 4, 9), dim3(32, 8)>>>(conv_W, Wh);
    xh_prep<<<(N_NODES * CH / 4 + TB - 1) / TB, TB>>>(x, xh);
    zero_deg_cursor<<<(N_NODES + TB - 1) / TB, TB>>>(deg, cursor);
    count_deg<<<(N_EDGES / 4 + TB - 1) / TB, TB>>>(edge_dst, deg);
    scan_blocks<<<scanBlocks, 1024>>>(deg, rowptr, bsums);
    add_boff<<<scanBlocks, 1024>>>(rowptr, bsums, scanBlocks);
    scatter_edges<<<(N_EDGES + TB - 1) / TB, TB>>>(edge_src, edge_dst, rowptr, cursor, csrsrc);

    // ping-pong: xh -> hA -> hB -> hA
    gin_layer<<<mlpBlocks, 256, MLP_SMEM>>>(xh, Wh,                conv_b,          rowptr, csrsrc, hA, N_NODES);
    gin_layer<<<mlpBlocks, 256, MLP_SMEM>>>(hA, Wh + 3 * CH * CH, conv_b + 3 * CH, rowptr, csrsrc, hB, N_NODES);
    gin_layer<<<mlpBlocks, 256, MLP_SMEM>>>(hB, Wh + 6 * CH * CH, conv_b + 6 * CH, rowptr, csrsrc, hA, N_NODES);

    pool_head<<<N_GRAPHS, 128>>>(hA, graph_id, d1_W, d1_b, d2_W, d2_b, out);
}

// round 10
// speedup vs baseline: 1.3247x; 1.3247x over previous
#include <cuda_runtime.h>
#include <cuda_fp16.h>
#include <cstdint>
#include <math.h>

#define N_NODES 50000
#define N_EDGES 625000
#define N_GRAPHS 256
#define CH 128
#define N_OUT 10

// ---------------- scratch (no allocations allowed) ----------------
__device__ __half g_xh[N_NODES * CH];
__device__ __half g_z [N_NODES * CH];
__device__ __half g_h [N_NODES * CH];
__device__ __half g_Wh[9 * CH * CH];   // fp16, transposed [n][k]

__device__ int   g_deg   [N_NODES];
__device__ int   g_cursor[N_NODES];
__device__ int   g_rowptr[N_NODES + 1];
__device__ int   g_csrsrc[N_EDGES];
__device__ int   g_bsums [64];

// ---------------- fused prep: wh transpose+cvt | xh cvt | zero -------------
// blocks [0,144): wh_prep (9 mats x 16 tiles); [144, 144+6250): xh; rest: zero
#define WH_BLOCKS 144
#define XH_BLOCKS ((N_NODES * CH / 4 + 255) / 256)   // 6250
#define ZERO_BLOCKS ((N_NODES + 255) / 256)          // 196
#define PREP_BLOCKS (WH_BLOCKS + XH_BLOCKS + ZERO_BLOCKS)

__global__ __launch_bounds__(256) void prep_all(
    const float* __restrict__ W, __half* __restrict__ Wh,
    const float* __restrict__ x, __half* __restrict__ xh,
    int* __restrict__ deg, int* __restrict__ cursor)
{
    int b = blockIdx.x;
    if (b < WH_BLOCKS) {
        // wh: matrix g = b/16, tile = b%16 -> (kt, nt)
        __shared__ float tile[32][33];
        int g = b >> 4;
        int t = b & 15;
        int kt = (t & 3) * 32, nt = (t >> 2) * 32;
        int tx = threadIdx.x & 31, ty = threadIdx.x >> 5;  // 32 x 8
        const float* Wg = W + g * CH * CH;
        __half* Whg = Wh + g * CH * CH;
#pragma unroll
        for (int i = 0; i < 32; i += 8)
            tile[ty + i][tx] = Wg[(kt + ty + i) * CH + nt + tx];
        __syncthreads();
#pragma unroll
        for (int i = 0; i < 32; i += 8)
            Whg[(nt + ty + i) * CH + kt + tx] = __float2half_rn(tile[tx][ty + i]);
    } else if (b < WH_BLOCKS + XH_BLOCKS) {
        int i = (b - WH_BLOCKS) * 256 + threadIdx.x;
        if (i < (N_NODES * CH) / 4) {
            float4 v = *(const float4*)(x + (size_t)i * 4);
            __half2 h0 = __floats2half2_rn(v.x, v.y);
            __half2 h1 = __floats2half2_rn(v.z, v.w);
            uint2 o;
            o.x = *(uint32_t*)&h0;
            o.y = *(uint32_t*)&h1;
            *(uint2*)(xh + (size_t)i * 4) = o;
        }
    } else {
        int i = (b - WH_BLOCKS - XH_BLOCKS) * 256 + threadIdx.x;
        if (i < N_NODES) { deg[i] = 0; cursor[i] = 0; }
    }
}

// ---------------- CSR build ----------------
// MLP=4: each thread front-loads 4 int4 (16 edges), then atomics
__global__ void count_deg(const int* __restrict__ dst, int* __restrict__ deg) {
    const int n4 = N_EDGES / 4;             // 156250 int4
    int base = (blockIdx.x * blockDim.x + threadIdx.x) * 4;
    if (base >= n4) return;
    int4 d0 = ((const int4*)dst)[base];
    int4 d1 = (base + 1 < n4) ? ((const int4*)dst)[base + 1] : make_int4(-1, -1, -1, -1);
    int4 d2 = (base + 2 < n4) ? ((const int4*)dst)[base + 2] : make_int4(-1, -1, -1, -1);
    int4 d3 = (base + 3 < n4) ? ((const int4*)dst)[base + 3] : make_int4(-1, -1, -1, -1);
    atomicAdd(&deg[d0.x], 1); atomicAdd(&deg[d0.y], 1);
    atomicAdd(&deg[d0.z], 1); atomicAdd(&deg[d0.w], 1);
    if (d1.x >= 0) { atomicAdd(&deg[d1.x], 1); atomicAdd(&deg[d1.y], 1);
                     atomicAdd(&deg[d1.z], 1); atomicAdd(&deg[d1.w], 1); }
    if (d2.x >= 0) { atomicAdd(&deg[d2.x], 1); atomicAdd(&deg[d2.y], 1);
                     atomicAdd(&deg[d2.z], 1); atomicAdd(&deg[d2.w], 1); }
    if (d3.x >= 0) { atomicAdd(&deg[d3.x], 1); atomicAdd(&deg[d3.y], 1);
                     atomicAdd(&deg[d3.z], 1); atomicAdd(&deg[d3.w], 1); }
}

__global__ void scan_blocks(const int* __restrict__ deg, int* __restrict__ rowptr,
                            int* __restrict__ bsums) {
    __shared__ int wsum[32];
    int gid = blockIdx.x * 1024 + threadIdx.x;
    int v = (gid < N_NODES) ? deg[gid] : 0;
    int lane = threadIdx.x & 31, wid = threadIdx.x >> 5;
    int x = v;
#pragma unroll
    for (int o = 1; o < 32; o <<= 1) {
        int y = __shfl_up_sync(0xffffffffu, x, o);
        if (lane >= o) x += y;
    }
    if (lane == 31) wsum[wid] = x;
    __syncthreads();
    if (wid == 0) {
        int s = wsum[lane];
#pragma unroll
        for (int o = 1; o < 32; o <<= 1) {
            int y = __shfl_up_sync(0xffffffffu, s, o);
            if (lane >= o) s += y;
        }
        wsum[lane] = s;
    }
    __syncthreads();
    int base = (wid > 0) ? wsum[wid - 1] : 0;
    int incl = base + x;
    if (gid < N_NODES) rowptr[gid] = incl - v;
    if (threadIdx.x == 1023) bsums[blockIdx.x] = incl;
}

__global__ void add_boff(int* __restrict__ rowptr, const int* __restrict__ bsums, int nblocks) {
    __shared__ int pre;
    if (threadIdx.x == 0) {
        int run = 0;
        for (int i = 0; i < (int)blockIdx.x; i++) run += bsums[i];
        pre = run;
        if ((int)blockIdx.x == nblocks - 1)
            rowptr[N_NODES] = run + bsums[nblocks - 1];
    }
    __syncthreads();
    int gid = blockIdx.x * 1024 + threadIdx.x;
    if (gid < N_NODES) rowptr[gid] += pre;
}

__global__ void scatter_edges(const int* __restrict__ src, const int* __restrict__ dst,
                              const int* __restrict__ rowptr, int* __restrict__ cursor,
                              int* __restrict__ csrsrc) {
    int e = blockIdx.x * blockDim.x + threadIdx.x;
    if (e >= N_EDGES) return;
    int d = dst[e];
    int slot = rowptr[d] + atomicAdd(&cursor[d], 1);
    csrsrc[slot] = src[e];
}

// ---------------- aggregation (fp16 in/out, fp32 accum, 2x unroll) ---------
__global__ void agg_kernel(const __half* __restrict__ h, __half* __restrict__ z,
                           const int* __restrict__ rowptr, const int* __restrict__ csrsrc) {
    int warp = (blockIdx.x * blockDim.x + threadIdx.x) >> 5;
    int lane = threadIdx.x & 31;
    if (warp >= N_NODES) return;
    const uint2* hv = (const uint2*)h;
    uint2 s = hv[warp * 32 + lane];
    float2 a0 = __half22float2(*(__half2*)&s.x);
    float2 a1 = __half22float2(*(__half2*)&s.y);
    int beg = rowptr[warp], end = rowptr[warp + 1];
    int i = beg;
    for (; i + 1 < end; i += 2) {
        int s0 = csrsrc[i], s1 = csrsrc[i + 1];
        uint2 w0 = hv[s0 * 32 + lane];
        uint2 w1 = hv[s1 * 32 + lane];
        float2 u0 = __half22float2(*(__half2*)&w0.x);
        float2 u1 = __half22float2(*(__half2*)&w0.y);
        float2 v0 = __half22float2(*(__half2*)&w1.x);
        float2 v1 = __half22float2(*(__half2*)&w1.y);
        a0.x += u0.x + v0.x; a0.y += u0.y + v0.y;
        a1.x += u1.x + v1.x; a1.y += u1.y + v1.y;
    }
    if (i < end) {
        int s0 = csrsrc[i];
        uint2 w0 = hv[s0 * 32 + lane];
        float2 u0 = __half22float2(*(__half2*)&w0.x);
        float2 u1 = __half22float2(*(__half2*)&w0.y);
        a0.x += u0.x; a0.y += u0.y; a1.x += u1.x; a1.y += u1.y;
    }
    __half2 o0 = __floats2half2_rn(a0.x, a0.y);
    __half2 o1 = __floats2half2_rn(a1.x, a1.y);
    uint2 o;
    o.x = *(uint32_t*)&o0;
    o.y = *(uint32_t*)&o1;
    ((uint2*)z)[warp * 32 + lane] = o;
}

// ---------------- fused 3-layer MLP (round-8 winner, unchanged) ------------
#define HS 136
#define ACT_SZ (64 * HS)
#define WB_SZ  (128 * HS)
#define MLP_SMEM ((2 * ACT_SZ + 2 * WB_SZ) * 2)   // 104448 B

__device__ __forceinline__ void mma16816(float* d, uint32_t a0, uint32_t a1,
                                         uint32_t a2, uint32_t a3,
                                         uint32_t b0, uint32_t b1) {
    asm volatile(
        "mma.sync.aligned.m16n8k16.row.col.f32.f16.f16.f32 "
        "{%0,%1,%2,%3}, {%4,%5,%6,%7}, {%8,%9}, {%0,%1,%2,%3};"
        : "+f"(d[0]), "+f"(d[1]), "+f"(d[2]), "+f"(d[3])
        : "r"(a0), "r"(a1), "r"(a2), "r"(a3), "r"(b0), "r"(b1));
}

__device__ __forceinline__ void ldsm_x4(uint32_t& r0, uint32_t& r1, uint32_t& r2,
                                        uint32_t& r3, uint32_t addr) {
    asm volatile("ldmatrix.sync.aligned.m8n8.x4.shared.b16 {%0,%1,%2,%3}, [%4];"
        : "=r"(r0), "=r"(r1), "=r"(r2), "=r"(r3) : "r"(addr));
}

__device__ __forceinline__ void cp_async16(uint32_t saddr, const void* gptr, int src_sz) {
    asm volatile("cp.async.cg.shared.global [%0], [%1], 16, %2;"
        :: "r"(saddr), "l"(gptr), "r"(src_sz));
}

__global__ __launch_bounds__(256) void gin_mlp(
    const __half* __restrict__ A, const __half* __restrict__ Wh3,
    const float* __restrict__ bias3,
    __half* __restrict__ C, int M)
{
    extern __shared__ __align__(16) char smem[];
    __half* actBuf = (__half*)smem;                 // [2][64][HS]
    __half* wBuf   = actBuf + 2 * ACT_SZ;           // [2][128][HS]

    int tid = threadIdx.x;
    int row0 = blockIdx.x * 64;

    uint32_t actB = (uint32_t)__cvta_generic_to_shared(actBuf);
    uint32_t wB   = (uint32_t)__cvta_generic_to_shared(wBuf);

#pragma unroll
    for (int it = 0; it < 4; it++) {
        int q = tid + it * 256;
        int r = q >> 4, k8 = q & 15;
        int gr = row0 + r;
        cp_async16(actB + ((r * HS + k8 * 8) << 1),
                   A + (size_t)gr * 128 + k8 * 8, (gr < M) ? 16 : 0);
    }
#pragma unroll
    for (int it = 0; it < 8; it++) {
        int q = tid + it * 256;
        int n = q >> 4, k8 = q & 15;
        cp_async16(wB + ((n * HS + k8 * 8) << 1),
                   Wh3 + (size_t)n * 128 + k8 * 8, 16);
    }
    asm volatile("cp.async.commit_group;");
#pragma unroll
    for (int it = 0; it < 8; it++) {
        int q = tid + it * 256;
        int n = q >> 4, k8 = q & 15;
        cp_async16(wB + ((WB_SZ + n * HS + k8 * 8) << 1),
                   Wh3 + CH * CH + (size_t)n * 128 + k8 * 8, 16);
    }
    asm volatile("cp.async.commit_group;");
    asm volatile("cp.async.wait_group 1;");
    __syncthreads();

    int lane = tid & 31, w = tid >> 5;
    int wm = w >> 2, wn = w & 3;
    int m0 = wm * 32, n0 = wn * 32;
    int grp = lane >> 2, tig = lane & 3;

    uint32_t aPat[2], bPat[2];
#pragma unroll
    for (int mt = 0; mt < 2; mt++)
        aPat[mt] = (uint32_t)((m0 + mt * 16 + (lane & 15)) * HS + (lane >> 4) * 8);
#pragma unroll
    for (int jj = 0; jj < 2; jj++)
        bPat[jj] = (uint32_t)((n0 + jj * 16 + (lane & 7) + ((lane >> 4) << 3)) * HS +
                              ((lane >> 3) & 1) * 8);

#pragma unroll
    for (int l = 0; l < 3; l++) {
        uint32_t aBase = actB + ((l & 1) ? (ACT_SZ << 1) : 0);
        uint32_t bBase = wB + ((l & 1) ? (WB_SZ << 1) : 0);

        float acc[2][4][4];
#pragma unroll
        for (int mt = 0; mt < 2; mt++)
#pragma unroll
            for (int j = 0; j < 4; j++)
#pragma unroll
                for (int i = 0; i < 4; i++) acc[mt][j][i] = 0.0f;

#pragma unroll
        for (int ks = 0; ks < 8; ks++) {
            uint32_t af[2][4];
#pragma unroll
            for (int mt = 0; mt < 2; mt++)
                ldsm_x4(af[mt][0], af[mt][1], af[mt][2], af[mt][3],
                        aBase + (aPat[mt] << 1) + ks * 32);
#pragma unroll
            for (int jj = 0; jj < 2; jj++) {
                uint32_t b0, b1, b2, b3;
                ldsm_x4(b0, b1, b2, b3, bBase + (bPat[jj] << 1) + ks * 32);
                mma16816(acc[0][jj * 2],     af[0][0], af[0][1], af[0][2], af[0][3], b0, b1);
                mma16816(acc[1][jj * 2],     af[1][0], af[1][1], af[1][2], af[1][3], b0, b1);
                mma16816(acc[0][jj * 2 + 1], af[0][0], af[0][1], af[0][2], af[0][3], b2, b3);
                mma16816(acc[1][jj * 2 + 1], af[1][0], af[1][1], af[1][2], af[1][3], b2, b3);
            }
        }

        const float* bias = bias3 + l * CH;
        if (l < 2) {
            __syncthreads();
            __half* actN = actBuf + ((l & 1) ? 0 : ACT_SZ);
#pragma unroll
            for (int mt = 0; mt < 2; mt++) {
                int rloc = m0 + mt * 16 + grp;
#pragma unroll
                for (int j = 0; j < 4; j++) {
                    int c = n0 + (j >> 1) * 16 + (j & 1) * 8 + tig * 2;
                    float bx = __ldg(bias + c), by = __ldg(bias + c + 1);
                    float v0 = fmaxf(acc[mt][j][0] + bx, 0.f);
                    float v1 = fmaxf(acc[mt][j][1] + by, 0.f);
                    float v2 = fmaxf(acc[mt][j][2] + bx, 0.f);
                    float v3 = fmaxf(acc[mt][j][3] + by, 0.f);
                    *(__half2*)(actN + rloc * HS + c)       = __floats2half2_rn(v0, v1);
                    *(__half2*)(actN + (rloc + 8) * HS + c) = __floats2half2_rn(v2, v3);
                }
            }
            if (l == 0) {
#pragma unroll
                for (int it = 0; it < 8; it++) {
                    int q = tid + it * 256;
                    int n = q >> 4, k8 = q & 15;
                    cp_async16(wB + ((n * HS + k8 * 8) << 1),
                               Wh3 + 2 * CH * CH + (size_t)n * 128 + k8 * 8, 16);
                }
                asm volatile("cp.async.commit_group;");
                asm volatile("cp.async.wait_group 1;");
            } else {
                asm volatile("cp.async.wait_group 0;");
            }
            __syncthreads();
        } else {
#pragma unroll
            for (int mt = 0; mt < 2; mt++) {
                int r = row0 + m0 + mt * 16 + grp;
#pragma unroll
                for (int j = 0; j < 4; j++) {
                    int c = n0 + (j >> 1) * 16 + (j & 1) * 8 + tig * 2;
                    float bx = __ldg(bias + c), by = __ldg(bias + c + 1);
                    if (r < M)
                        *(__half2*)(C + (size_t)r * 128 + c) =
                            __floats2half2_rn(acc[mt][j][0] + bx, acc[mt][j][1] + by);
                    if (r + 8 < M)
                        *(__half2*)(C + (size_t)(r + 8) * 128 + c) =
                            __floats2half2_rn(acc[mt][j][2] + bx, acc[mt][j][3] + by);
                }
            }
        }
    }
}

// ---------------- fused pool (sorted segments) + head ----------------------
__global__ void pool_head(const __half* __restrict__ h, const int* __restrict__ gid,
                          const float* __restrict__ W1, const float* __restrict__ b1,
                          const float* __restrict__ W2, const float* __restrict__ b2,
                          float* __restrict__ out) {
    int g = blockIdx.x;
    int t = threadIdx.x;
    __shared__ float p[128];
    __shared__ float h1[128];
    __shared__ float logits[N_OUT];

    int lo = 0, hi = N_NODES;
    while (lo < hi) { int mid = (lo + hi) >> 1; if (gid[mid] < g) lo = mid + 1; else hi = mid; }
    int start = lo;
    lo = start; hi = N_NODES;
    while (lo < hi) { int mid = (lo + hi) >> 1; if (gid[mid] < g + 1) lo = mid + 1; else hi = mid; }
    int end = lo;

    float s = 0.0f;
    for (int n = start; n < end; n++)
        s += __half2float(h[(size_t)n * 128 + t]);
    int cnt = end - start;
    p[t] = s / fmaxf((float)cnt, 1.0f);
    __syncthreads();

    float acc = b1[t];
#pragma unroll 8
    for (int k = 0; k < 128; k++) acc += p[k] * W1[k * 128 + t];
    h1[t] = fmaxf(acc, 0.0f);
    __syncthreads();

    if (t < N_OUT) {
        float a = b2[t];
#pragma unroll 8
        for (int k = 0; k < 128; k++) a += h1[k] * W2[k * N_OUT + t];
        logits[t] = a;
    }
    __syncthreads();

    if (t == 0) {
        float m = -1e30f;
#pragma unroll
        for (int o = 0; o < N_OUT; o++) m = fmaxf(m, logits[o]);
        float e[N_OUT], sum = 0.0f;
#pragma unroll
        for (int o = 0; o < N_OUT; o++) { e[o] = __expf(logits[o] - m); sum += e[o]; }
        float inv = 1.0f / sum;
#pragma unroll
        for (int o = 0; o < N_OUT; o++) out[g * N_OUT + o] = e[o] * inv;
    }
}

// ---------------- launch ----------------
extern "C" void kernel_launch(void* const* d_in, const int* in_sizes, int n_in,
                              void* d_out, int out_size) {
    const float* x        = (const float*)d_in[0];
    const int*   edge_src = (const int*)  d_in[1];
    const int*   edge_dst = (const int*)  d_in[2];
    const int*   graph_id = (const int*)  d_in[3];
    const float* conv_W   = (const float*)d_in[4];
    const float* conv_b   = (const float*)d_in[5];
    const float* d1_W     = (const float*)d_in[6];
    const float* d1_b     = (const float*)d_in[7];
    const float* d2_W     = (const float*)d_in[8];
    const float* d2_b     = (const float*)d_in[9];
    float* out = (float*)d_out;

    __half *xh, *z, *h, *Wh;
    int *deg, *cursor, *rowptr, *csrsrc, *bsums;
    cudaGetSymbolAddress((void**)&xh,     g_xh);
    cudaGetSymbolAddress((void**)&z,      g_z);
    cudaGetSymbolAddress((void**)&h,      g_h);
    cudaGetSymbolAddress((void**)&Wh,     g_Wh);
    cudaGetSymbolAddress((void**)&deg,    g_deg);
    cudaGetSymbolAddress((void**)&cursor, g_cursor);
    cudaGetSymbolAddress((void**)&rowptr, g_rowptr);
    cudaGetSymbolAddress((void**)&csrsrc, g_csrsrc);
    cudaGetSymbolAddress((void**)&bsums,  g_bsums);

    cudaFuncSetAttribute(gin_mlp, cudaFuncAttributeMaxDynamicSharedMemorySize, MLP_SMEM);

    const int TB = 256;
    const int scanBlocks = (N_NODES + 1023) / 1024;  // 49
    const int aggBlocks  = (N_NODES * 32 + TB - 1) / TB;
    const int mlpBlocks  = (N_NODES + 63) / 64;      // 782
    const int cdBlocks   = (N_EDGES / 16 + TB - 1) / TB;  // MLP=4

    prep_all<<<PREP_BLOCKS, 256>>>(conv_W, Wh, x, xh, deg, cursor);
    count_deg<<<cdBlocks, TB>>>(edge_dst, deg);
    scan_blocks<<<scanBlocks, 1024>>>(deg, rowptr, bsums);
    add_boff<<<scanBlocks, 1024>>>(rowptr, bsums, scanBlocks);
    scatter_edges<<<(N_EDGES + TB - 1) / TB, TB>>>(edge_src, edge_dst, rowptr, cursor, csrsrc);

    const __half* hin = xh;
    for (int l = 0; l < 3; l++) {
        agg_kernel<<<aggBlocks, TB>>>(hin, z, rowptr, csrsrc);
        gin_mlp<<<mlpBlocks, 256, MLP_SMEM>>>(z,
            Wh + (size_t)l * 3 * CH * CH, conv_b + (size_t)l * 3 * CH, h, N_NODES);
        hin = h;
    }

    pool_head<<<N_GRAPHS, 128>>>(h, graph_id, d1_W, d1_b, d2_W, d2_b, out);
}